// round 8
// baseline (speedup 1.0000x reference)
#include <cuda_runtime.h>

// Fixed dataset geometry: 512x512 grid mesh, batch 32.
#define W 512
#define H 512
#define NV (H * W)
#define FC (W * 3)          // 1536 float columns per grid row
#define FCG 12              // warp covers 128 float-cols (32 float4s)
#define RPW 16              // rows per warp chunk
#define CHUNKS (H / RPW)    // 32
#define WPB (FCG * CHUNKS)  // warps per batch = 384
#define BLOCK_THREADS 256
#define WARPS_PER_BLOCK (BLOCK_THREADS / 32)

__global__ void zero_out_kernel(float* out) {
    if (threadIdx.x == 0) out[0] = 0.0f;
}

// Walk RPW rows for one warp. EDGE = column group touches the grid's left or
// right boundary (cg 0 / FCG-1). Interior warps: maskless, constant coefs.
template<bool EDGE>
__device__ __forceinline__ float walk(const float* __restrict__ vb,
                                      int fidx, int lane, int fbase,
                                      bool doL, bool doR, int r0)
{
    const unsigned FULL = 0xFFFFFFFFu;

    // Edge-only per-column masks / coefficients.
    float mL[4], mR[4], cMid[4], cTop[4], cBot[4];
    if (EDGE) {
#pragma unroll
        for (int t = 0; t < 4; t++) {
            int f = fbase + t;
            mL[t] = (f >= 3)     ? 1.0f : 0.0f;
            mR[t] = (f < FC - 3) ? 1.0f : 0.0f;
            cMid[t] = -1.0f / (2.0f + 2.0f * (mL[t] + mR[t]));
            cTop[t] = -1.0f / (1.0f + 2.0f * mL[t] + mR[t]);
            cBot[t] = -1.0f / (1.0f + mL[t] + 2.0f * mR[t]);
        }
    }

    // Row state: a = i-1, b = i, c = i+1; *m3/*p3 = shifted by -3/+3 floats.
    float4 a4, b4, c4;
    float ap3[3], bm3[3], bp3[3], cm3[3], cp3[3];
    float acc = 0.0f;

    auto load_row = [&](int r, float4& v4, float m3[3], float p3[3]) {
        const float4* rowp = (const float4*)(vb + (size_t)r * FC);
        v4 = __ldg(rowp + fidx);
        float4 hl = make_float4(0.f, 0.f, 0.f, 0.f);
        float4 hr = make_float4(0.f, 0.f, 0.f, 0.f);
        if (doL) hl = __ldg(rowp + fidx - 1);
        if (doR) hr = __ldg(rowp + fidx + 1);
        float uy = __shfl_up_sync(FULL, v4.y, 1);
        float uz = __shfl_up_sync(FULL, v4.z, 1);
        float uw = __shfl_up_sync(FULL, v4.w, 1);
        float dx = __shfl_down_sync(FULL, v4.x, 1);
        float dy = __shfl_down_sync(FULL, v4.y, 1);
        float dz = __shfl_down_sync(FULL, v4.z, 1);
        m3[0] = (lane == 0)  ? hl.y : uy;
        m3[1] = (lane == 0)  ? hl.z : uz;
        m3[2] = (lane == 0)  ? hl.w : uw;
        p3[0] = (lane == 31) ? hr.x : dx;
        p3[1] = (lane == 31) ? hr.y : dy;
        p3[2] = (lane == 31) ? hr.z : dz;
    };

    // phase: 0 = top row (mU=0), 1 = interior, 2 = bottom row (mD=0)
    auto compute = [&](int phase) {
        float bm[4] = {bm3[0], bm3[1], bm3[2], b4.x};
        float bp[4] = {b4.w,  bp3[0], bp3[1], bp3[2]};
        float ap[4] = {a4.w,  ap3[0], ap3[1], ap3[2]};
        float cm[4] = {cm3[0], cm3[1], cm3[2], c4.x};
        float av[4] = {a4.x, a4.y, a4.z, a4.w};
        float cv[4] = {c4.x, c4.y, c4.z, c4.w};
        float bv[4] = {b4.x, b4.y, b4.z, b4.w};
        float mU = (phase == 0) ? 0.0f : 1.0f;
        float mD = (phase == 2) ? 0.0f : 1.0f;
#pragma unroll
        for (int t = 0; t < 4; t++) {
            float Lv;
            if (EDGE) {
                float sl = fmaf(mD, cm[t], bm[t]);
                float sr = fmaf(mU, ap[t], bp[t]);
                float s  = fmaf(mU, av[t], mD * cv[t]);
                s = fmaf(mL[t], sl, s);
                s = fmaf(mR[t], sr, s);
                float coef = (phase == 0) ? cTop[t] : ((phase == 2) ? cBot[t] : cMid[t]);
                Lv = fmaf(coef, s, bv[t]);
            } else {
                float s;
                float coef;
                if (phase == 0) {        // left, right, down, down-left
                    s = (bm[t] + cm[t]) + (bp[t] + cv[t]);
                    coef = -(1.0f / 4.0f);
                } else if (phase == 2) { // left, right, up, up-right
                    s = (bm[t] + bp[t]) + (av[t] + ap[t]);
                    coef = -(1.0f / 4.0f);
                } else {                 // 6 neighbors
                    s = (bm[t] + cm[t]) + ((bp[t] + ap[t]) + (av[t] + cv[t]));
                    coef = -(1.0f / 6.0f);
                }
                Lv = fmaf(coef, s, bv[t]);
            }
            acc = fmaf(Lv, Lv, acc);
        }
    };

    auto rotate = [&]() {
        a4 = b4; b4 = c4;
#pragma unroll
        for (int t = 0; t < 3; t++) { ap3[t] = bp3[t]; bm3[t] = cm3[t]; bp3[t] = cp3[t]; }
    };

    // ---- preload rows r0-1 (a; clamped & masked for top chunk) and r0 (b) ----
    {
        int rm = (r0 > 0) ? r0 - 1 : 0;
        float dm[3];
        load_row(rm, a4, dm, ap3);
        load_row(r0, b4, bm3, bp3);
    }

    int i    = r0;
    int iend = r0 + RPW;

    if (r0 == 0) {                    // peel top boundary row
        load_row(1, c4, cm3, cp3);
        compute(0);
        rotate();
        i = 1;
    }

    int mainEnd = (iend == H) ? H - 1 : iend;
#pragma unroll 4
    for (; i < mainEnd; i++) {
        load_row(i + 1, c4, cm3, cp3);
        compute(1);
        rotate();
    }

    if (iend == H) {                  // peel bottom boundary row (a=H-2, b=H-1)
        compute(2);
    }

    return acc;
}

__global__ __launch_bounds__(BLOCK_THREADS, 4)
void lap_kernel(const float* __restrict__ verts, float* __restrict__ out, float scale)
{
    const unsigned FULL = 0xFFFFFFFFu;
    int lane = threadIdx.x & 31;
    int gw   = (blockIdx.x * BLOCK_THREADS + threadIdx.x) >> 5;

    int bb  = gw / WPB;
    int rem = gw - bb * WPB;
    int cg  = rem % FCG;
    int rc  = rem / FCG;
    int r0  = rc * RPW;

    const float* vb = verts + (size_t)bb * NV * 3;
    int fidx  = cg * 32 + lane;          // float4 index within a grid row
    int fbase = cg * 128 + lane * 4;     // first float column owned by this lane
    bool doL = (lane == 0)  && (cg > 0);
    bool doR = (lane == 31) && (cg < FCG - 1);
    bool edge = (cg == 0) || (cg == FCG - 1);

    float acc = edge ? walk<true >(vb, fidx, lane, fbase, doL, doR, r0)
                     : walk<false>(vb, fidx, lane, fbase, doL, doR, r0);

    // ---- reduce: warp -> block -> global atomic ----
#pragma unroll
    for (int off = 16; off > 0; off >>= 1)
        acc += __shfl_xor_sync(FULL, acc, off);

    __shared__ float warp_sums[WARPS_PER_BLOCK];
    int wid = threadIdx.x >> 5;
    if (lane == 0) warp_sums[wid] = acc;
    __syncthreads();

    if (wid == 0) {
        float s = (lane < WARPS_PER_BLOCK) ? warp_sums[lane] : 0.0f;
#pragma unroll
        for (int off = 4; off > 0; off >>= 1)
            s += __shfl_xor_sync(FULL, s, off);
        if (lane == 0) atomicAdd(out, s * scale);
    }
}

extern "C" void kernel_launch(void* const* d_in, const int* in_sizes, int n_in,
                              void* d_out, int out_size) {
    const float* verts = (const float*)d_in[0];
    int B = in_sizes[0] / (NV * 3);

    float* out = (float*)d_out;
    zero_out_kernel<<<1, 32>>>(out);

    int total_warps  = B * WPB;
    int total_blocks = total_warps / WARPS_PER_BLOCK;   // 1536
    float scale = 1.0f / ((float)B * (float)NV);
    lap_kernel<<<total_blocks, BLOCK_THREADS>>>(verts, out, scale);
}

// round 9
// speedup vs baseline: 1.1261x; 1.1261x over previous
#include <cuda_runtime.h>

// Fixed dataset geometry: 512x512 grid mesh, batch 32.
#define W 512
#define H 512
#define NV (H * W)
#define FC (W * 3)          // 1536 float columns per grid row
#define FCG 6               // lane owns 8 float-cols; warp covers 256
#define RPW 32              // rows per warp chunk
#define CHUNKS (H / RPW)    // 16
#define WPB (FCG * CHUNKS)  // warps per batch = 96
#define BLOCK_THREADS 128
#define WARPS_PER_BLOCK (BLOCK_THREADS / 32)

__global__ void zero_out_kernel(float* out) {
    if (threadIdx.x == 0) out[0] = 0.0f;
}

// Walk RPW rows of the stencil for one warp. EDGE = warp's column group touches
// the left/right grid boundary (cg 0 or FCG-1); interior warps use constant
// coefficients and no masks.
template<bool EDGE>
__device__ __forceinline__ float walk(const float* __restrict__ vb,
                                      int fidx0, int lane, int fbase,
                                      bool doL, bool doR, int r0)
{
    const unsigned FULL = 0xFFFFFFFFu;

    float mL[8], mR[8];
    if (EDGE) {
#pragma unroll
        for (int t = 0; t < 8; t++) {
            int f = fbase + t;
            mL[t] = (f >= 3)     ? 1.0f : 0.0f;
            mR[t] = (f < FC - 3) ? 1.0f : 0.0f;
        }
    }

    // Row state: a = i-1, b = i, c = i+1 (8 float-cols each).
    // *m3 = row[f-3..f-1] (left-shift), *p3 = row[f+8..f+10] (right-shift).
    float a[8], b[8], c[8];
    float ap3[3], bm3[3], bp3[3], cm3[3], cp3[3];
    float acc[4] = {0.f, 0.f, 0.f, 0.f};    // 4 independent FMA chains

    auto load_row = [&](int r, float row[8], float m3[3], float p3[3]) {
        const float4* rowp = (const float4*)(vb + (size_t)r * FC);
        float4 v0 = __ldg(rowp + fidx0);
        float4 v1 = __ldg(rowp + fidx0 + 1);
        float4 hl = make_float4(0.f, 0.f, 0.f, 0.f);
        float4 hr = make_float4(0.f, 0.f, 0.f, 0.f);
        if (doL) hl = __ldg(rowp + fidx0 - 1);
        if (doR) hr = __ldg(rowp + fidx0 + 2);
        row[0] = v0.x; row[1] = v0.y; row[2] = v0.z; row[3] = v0.w;
        row[4] = v1.x; row[5] = v1.y; row[6] = v1.z; row[7] = v1.w;
        float u0 = __shfl_up_sync(FULL, v1.y, 1);
        float u1 = __shfl_up_sync(FULL, v1.z, 1);
        float u2 = __shfl_up_sync(FULL, v1.w, 1);
        float d0 = __shfl_down_sync(FULL, v0.x, 1);
        float d1 = __shfl_down_sync(FULL, v0.y, 1);
        float d2 = __shfl_down_sync(FULL, v0.z, 1);
        m3[0] = (lane == 0)  ? hl.y : u0;
        m3[1] = (lane == 0)  ? hl.z : u1;
        m3[2] = (lane == 0)  ? hl.w : u2;
        p3[0] = (lane == 31) ? hr.x : d0;
        p3[1] = (lane == 31) ? hr.y : d1;
        p3[2] = (lane == 31) ? hr.z : d2;
    };

    auto compute_mid = [&]() {
#pragma unroll
        for (int t = 0; t < 8; t++) {
            float bmv = (t < 3) ? bm3[t] : b[t - 3];
            float bpv = (t < 5) ? b[t + 3] : bp3[t - 5];
            float apv = (t < 5) ? a[t + 3] : ap3[t - 5];
            float cmv = (t < 3) ? cm3[t] : c[t - 3];
            float Lv;
            if (EDGE) {
                float s = a[t] + c[t];
                s = fmaf(mL[t], bmv + cmv, s);
                s = fmaf(mR[t], bpv + apv, s);
                float coef = (mL[t] * mR[t] != 0.0f) ? (-1.0f / 6.0f) : (-1.0f / 4.0f);
                Lv = fmaf(coef, s, b[t]);
            } else {
                float s = (bmv + cmv) + ((bpv + apv) + (a[t] + c[t]));
                Lv = fmaf(-(1.0f / 6.0f), s, b[t]);
            }
            acc[t & 3] = fmaf(Lv, Lv, acc[t & 3]);
        }
    };

    auto compute_top = [&]() {        // row 0: neighbors left, right, down, down-left
#pragma unroll
        for (int t = 0; t < 8; t++) {
            float bmv = (t < 3) ? bm3[t] : b[t - 3];
            float bpv = (t < 5) ? b[t + 3] : bp3[t - 5];
            float cmv = (t < 3) ? cm3[t] : c[t - 3];
            float Lv;
            if (EDGE) {
                float s = c[t];
                s = fmaf(mL[t], bmv + cmv, s);
                s = fmaf(mR[t], bpv, s);
                float coef = -1.0f / (1.0f + 2.0f * mL[t] + mR[t]);
                Lv = fmaf(coef, s, b[t]);
            } else {
                float s = (bmv + cmv) + (bpv + c[t]);
                Lv = fmaf(-(1.0f / 4.0f), s, b[t]);
            }
            acc[t & 3] = fmaf(Lv, Lv, acc[t & 3]);
        }
    };

    auto compute_bot = [&]() {        // row H-1: neighbors left, right, up, up-right
#pragma unroll
        for (int t = 0; t < 8; t++) {
            float bmv = (t < 3) ? bm3[t] : b[t - 3];
            float bpv = (t < 5) ? b[t + 3] : bp3[t - 5];
            float apv = (t < 5) ? a[t + 3] : ap3[t - 5];
            float Lv;
            if (EDGE) {
                float s = a[t];
                s = fmaf(mL[t], bmv, s);
                s = fmaf(mR[t], bpv + apv, s);
                float coef = -1.0f / (1.0f + mL[t] + 2.0f * mR[t]);
                Lv = fmaf(coef, s, b[t]);
            } else {
                float s = (bmv + bpv) + (a[t] + apv);
                Lv = fmaf(-(1.0f / 4.0f), s, b[t]);
            }
            acc[t & 3] = fmaf(Lv, Lv, acc[t & 3]);
        }
    };

    auto rotate = [&]() {
#pragma unroll
        for (int t = 0; t < 8; t++) { a[t] = b[t]; b[t] = c[t]; }
#pragma unroll
        for (int t = 0; t < 3; t++) { ap3[t] = bp3[t]; bm3[t] = cm3[t]; bp3[t] = cp3[t]; }
    };

    // ---- preload rows r0-1 (a; clamped, unused for top chunk) and r0 (b) ----
    {
        int rm = (r0 > 0) ? r0 - 1 : 0;
        float dm[3];
        load_row(rm, a, dm, ap3);
        load_row(r0, b, bm3, bp3);
    }

    int i    = r0;
    int iend = r0 + RPW;

    if (r0 == 0) {                    // peel top boundary row
        load_row(1, c, cm3, cp3);
        compute_top();
        rotate();
        i = 1;
    }

    int mainEnd = (iend == H) ? H - 1 : iend;
#pragma unroll 4
    for (; i < mainEnd; i++) {
        load_row(i + 1, c, cm3, cp3);
        compute_mid();
        rotate();
    }

    if (iend == H) {                  // peel bottom boundary row (a=H-2, b=H-1)
        compute_bot();
    }

    return (acc[0] + acc[1]) + (acc[2] + acc[3]);
}

__global__ __launch_bounds__(BLOCK_THREADS, 6)
void lap_kernel(const float* __restrict__ verts, float* __restrict__ out, float scale)
{
    const unsigned FULL = 0xFFFFFFFFu;
    int lane = threadIdx.x & 31;
    int gw   = (blockIdx.x * BLOCK_THREADS + threadIdx.x) >> 5;

    int bb  = gw / WPB;
    int rem = gw - bb * WPB;
    int cg  = rem % FCG;
    int rc  = rem / FCG;
    int r0  = rc * RPW;

    const float* vb = verts + (size_t)bb * NV * 3;
    int fidx0 = cg * 64 + lane * 2;      // float4 index of lane's first vector
    int fbase = cg * 256 + lane * 8;     // first float column owned by this lane
    bool doL = (lane == 0)  && (cg > 0);
    bool doR = (lane == 31) && (cg < FCG - 1);
    bool edge = (cg == 0) || (cg == FCG - 1);

    float acc = edge ? walk<true >(vb, fidx0, lane, fbase, doL, doR, r0)
                     : walk<false>(vb, fidx0, lane, fbase, doL, doR, r0);

    // ---- reduce: warp -> block -> global atomic ----
#pragma unroll
    for (int off = 16; off > 0; off >>= 1)
        acc += __shfl_xor_sync(FULL, acc, off);

    __shared__ float warp_sums[WARPS_PER_BLOCK];
    int wid = threadIdx.x >> 5;
    if (lane == 0) warp_sums[wid] = acc;
    __syncthreads();

    if (threadIdx.x == 0) {
        float s = 0.0f;
#pragma unroll
        for (int k = 0; k < WARPS_PER_BLOCK; k++) s += warp_sums[k];
        atomicAdd(out, s * scale);
    }
}

extern "C" void kernel_launch(void* const* d_in, const int* in_sizes, int n_in,
                              void* d_out, int out_size) {
    const float* verts = (const float*)d_in[0];
    int B = in_sizes[0] / (NV * 3);

    float* out = (float*)d_out;
    zero_out_kernel<<<1, 32>>>(out);

    int total_warps  = B * WPB;                         // 3072
    int total_blocks = total_warps / WARPS_PER_BLOCK;   // 768 (single wave @ occ 6)
    float scale = 1.0f / ((float)B * (float)NV);
    lap_kernel<<<total_blocks, BLOCK_THREADS>>>(verts, out, scale);
}